// round 6
// baseline (speedup 1.0000x reference)
#include <cuda_runtime.h>
#include <cuda_bf16.h>

#define B_  64
#define Q_  900
#define T_  100
#define C_  256
#define INF_ 1e9f
#define NCH 29     // ceil(Q_/32); last chunk has 4 rows
#define COPYB 72   // transpose-copy blocks appended to hungarian launch

// Transposed cost scratch [B, T, Q] for contiguous row access in Hungarian.
__device__ float g_costT[B_ * T_ * Q_];
// Per (b, chunk, target-row) packed partial min: [orderable-key:32 | col:32]
__device__ unsigned long long g_rowpart[B_ * NCH * T_];

__device__ __forceinline__ unsigned int f32_orderable(float f) {
    unsigned int b = __float_as_uint(f);
    return (b & 0x80000000u) ? ~b : (b | 0x80000000u);
}

// ---------------------------------------------------------------------------
// Phase 1: cost matrix (costT layout only) + per-chunk row argmin.
// grid (29, B), 256 threads.
// ---------------------------------------------------------------------------
__global__ __launch_bounds__(256) void cost_kernel(
    const float* __restrict__ logits,   // [B,Q,C]
    const float* __restrict__ pboxes,   // [B,Q,4] cxcywh
    const int*   __restrict__ labels,   // [B,T]
    const float* __restrict__ tboxes)   // [B,T,4] cxcywh
{
    const int b  = blockIdx.y;
    const int q0 = blockIdx.x * 32;
    const int qcnt = min(32, Q_ - q0);
    const int tid = threadIdx.x;

    __shared__ float slog[32][257];
    __shared__ float stile[32][100];
    __shared__ float stb[100][4];
    __shared__ int   slab[100];
    __shared__ float spb[32][4];

    {
        const float* lg = logits + ((long)b * Q_ + q0) * C_;
        for (int i = tid * 4; i < qcnt * C_; i += 256 * 4) {
            float4 vv = *reinterpret_cast<const float4*>(lg + i);
            int r = i >> 8, c = i & 255;
            slog[r][c + 0] = vv.x; slog[r][c + 1] = vv.y;
            slog[r][c + 2] = vv.z; slog[r][c + 3] = vv.w;
        }
    }
    for (int i = tid; i < T_ * 4; i += 256)
        stb[i >> 2][i & 3] = tboxes[(long)b * T_ * 4 + i];
    for (int i = tid; i < T_; i += 256)
        slab[i] = labels[(long)b * T_ + i];
    for (int i = tid; i < qcnt * 4; i += 256)
        spb[i >> 2][i & 3] = pboxes[((long)b * Q_ + q0) * 4 + i];
    __syncthreads();

    for (int idx = tid; idx < qcnt * T_; idx += 256) {
        int qi = idx / T_;
        int t  = idx - qi * T_;
        float pcx = spb[qi][0], pcy = spb[qi][1], pw = spb[qi][2], ph = spb[qi][3];
        float tcx = stb[t][0],  tcy = stb[t][1],  tw = stb[t][2],  th = stb[t][3];

        float l1 = fabsf(pcx - tcx) + fabsf(pcy - tcy) + fabsf(pw - tw) + fabsf(ph - th);

        float ax0 = pcx - 0.5f * pw, ay0 = pcy - 0.5f * ph;
        float ax1 = pcx + 0.5f * pw, ay1 = pcy + 0.5f * ph;
        float bx0 = tcx - 0.5f * tw, by0 = tcy - 0.5f * th;
        float bx1 = tcx + 0.5f * tw, by1 = tcy + 0.5f * th;

        float areaA = (ax1 - ax0) * (ay1 - ay0);
        float areaB = (bx1 - bx0) * (by1 - by0);
        float ltx = fmaxf(ax0, bx0), lty = fmaxf(ay0, by0);
        float rbx = fminf(ax1, bx1), rby = fminf(ay1, by1);
        float iw = fmaxf(rbx - ltx, 0.f), ih = fmaxf(rby - lty, 0.f);
        float inter = iw * ih;
        float uni = areaA + areaB - inter;
        float iou = inter / uni;
        float ex0 = fminf(ax0, bx0), ey0 = fminf(ay0, by0);
        float ex1 = fmaxf(ax1, bx1), ey1 = fmaxf(ay1, by1);
        float enc = fmaxf(ex1 - ex0, 0.f) * fmaxf(ey1 - ey0, 0.f);
        float giou = iou - (enc - uni) / enc;

        stile[qi][t] = -slog[qi][slab[t]] + l1 - giou;
    }
    __syncthreads();

    // per-chunk target-row argmin -> packed partial (no atomics)
    if (tid < T_) {
        float best = INF_; int bq = 0;
        for (int qi = 0; qi < qcnt; qi++) {
            float c = stile[qi][tid];
            if (c < best) { best = c; bq = q0 + qi; }
        }
        g_rowpart[((long)b * NCH + blockIdx.x) * T_ + tid] =
            ((unsigned long long)f32_orderable(best) << 32) | (unsigned int)bq;
    }

    // transposed write, float4 over qi (900 % 4 == 0 -> aligned)
    for (int idx = tid; idx < T_ * 8; idx += 256) {
        int t   = idx >> 3;
        int seg = idx & 7;
        if (seg * 4 < qcnt) {
            float4 vv = make_float4(stile[seg * 4 + 0][t], stile[seg * 4 + 1][t],
                                    stile[seg * 4 + 2][t], stile[seg * 4 + 3][t]);
            *reinterpret_cast<float4*>(
                g_costT + ((long)b * T_ + t) * Q_ + q0 + seg * 4) = vv;
        }
    }
}

// ---------------------------------------------------------------------------
// Phase 2: blocks [0,64): JV Hungarian per batch.
//          blocks [64,64+COPYB): costT -> [B,Q,T] d_out transpose copy
//          (runs on idle SMs, hidden under hungarian's latency).
// ---------------------------------------------------------------------------
__global__ __launch_bounds__(256) void hungarian_kernel(float* __restrict__ out)
{
    const int tid  = threadIdx.x;

    if (blockIdx.x >= B_) {
        // ----- transpose copy path -----
        __shared__ float tile[32][104];   // pad 104: q-major stores conflict-free
        const int bc = blockIdx.x - B_;
        for (int tileId = bc; tileId < B_ * NCH; tileId += COPYB) {
            const int b  = tileId / NCH;
            const int ch = tileId - b * NCH;
            const int q0 = ch * 32;
            const int qcnt = min(32, Q_ - q0);
            // load: costT [t][q0..q0+qcnt) as float4 over q
            for (int idx = tid; idx < T_ * 8; idx += 256) {
                int t = idx >> 3, seg = idx & 7;
                if (seg * 4 < qcnt) {
                    float4 vv = *reinterpret_cast<const float4*>(
                        g_costT + ((long)b * T_ + t) * Q_ + q0 + seg * 4);
                    tile[seg * 4 + 0][t] = vv.x; tile[seg * 4 + 1][t] = vv.y;
                    tile[seg * 4 + 2][t] = vv.z; tile[seg * 4 + 3][t] = vv.w;
                }
            }
            __syncthreads();
            // store: cost rows [q][0..100) as float4 over t
            for (int idx = tid; idx < qcnt * 25; idx += 256) {
                int qi = idx / 25, s = idx - qi * 25;
                float4 vv = make_float4(tile[qi][4 * s + 0], tile[qi][4 * s + 1],
                                        tile[qi][4 * s + 2], tile[qi][4 * s + 3]);
                *reinterpret_cast<float4*>(
                    out + ((long)(b * Q_ + q0 + qi)) * T_ + 4 * s) = vv;
            }
            __syncthreads();
        }
        return;
    }

    // ----- Hungarian path -----
    const int b    = blockIdx.x;
    const int wid  = tid >> 5, lane = tid & 31;
    const float* CT = g_costT + (long)b * T_ * Q_;
    const bool owns = (tid < Q_ / 4);   // 225 scan threads, 4 contiguous cols each

    __shared__ float v[Q_];
    __shared__ int   pred[Q_];
    __shared__ int   y[Q_];      // col -> row (-1 free)
    __shared__ int   x[T_];      // row -> col
    __shared__ float rv[2][8];
    __shared__ int   ri[2][8];
    __shared__ int   col[T_];
    __shared__ int   rmin[T_];
    __shared__ int   freeRows[T_];
    __shared__ int   s_nfree;

    for (int j = tid; j < Q_; j += 256) { v[j] = 0.f; y[j] = -1; }

    if (tid < T_) {
        const unsigned long long* rp = g_rowpart + (long)b * NCH * T_ + tid;
        unsigned long long m = rp[0];
        #pragma unroll
        for (int c = 1; c < NCH; c++) {
            unsigned long long pk = rp[(long)c * T_];
            if (pk < m) m = pk;
        }
        rmin[tid] = (int)(unsigned int)(m & 0xFFFFFFFFULL);
    }
    __syncthreads();

    if (tid == 0) {
        int nf = 0;
        for (int i = 0; i < T_; i++) {
            int j = rmin[i];
            if (y[j] < 0) { y[j] = i; x[i] = j; }
            else          { x[i] = -1; freeRows[nf++] = i; }
        }
        s_nfree = nf;
    }
    __syncthreads();
    const int nfree = s_nfree;

    for (int fi = 0; fi < nfree; fi++) {
        const int f = freeRows[fi];
        float4 d = make_float4(INF_, INF_, INF_, INF_);
        unsigned int scm = 0;
        int   i1 = f;
        float h  = 0.f;
        const float* crow = CT + (long)f * Q_;
        float mu; int jstar;
        int pp = 0;

        while (true) {
            float bv = INF_; int bj = 0x7fffffff;
            if (owns) {
                const int j0 = tid << 2;
                float4 cv = __ldg((const float4*)(crow) + tid);
                float4 vv = *((const float4*)v + tid);
                if (!(scm & 1u)) {
                    float nd = cv.x - vv.x - h;
                    if (nd < d.x) { d.x = nd; pred[j0 + 0] = i1; }
                    if (d.x < bv) { bv = d.x; bj = j0 + 0; }
                }
                if (!(scm & 2u)) {
                    float nd = cv.y - vv.y - h;
                    if (nd < d.y) { d.y = nd; pred[j0 + 1] = i1; }
                    if (d.y < bv) { bv = d.y; bj = j0 + 1; }
                }
                if (!(scm & 4u)) {
                    float nd = cv.z - vv.z - h;
                    if (nd < d.z) { d.z = nd; pred[j0 + 2] = i1; }
                    if (d.z < bv) { bv = d.z; bj = j0 + 2; }
                }
                if (!(scm & 8u)) {
                    float nd = cv.w - vv.w - h;
                    if (nd < d.w) { d.w = nd; pred[j0 + 3] = i1; }
                    if (d.w < bv) { bv = d.w; bj = j0 + 3; }
                }
            }
            #pragma unroll
            for (int off = 16; off; off >>= 1) {
                float v2 = __shfl_down_sync(0xffffffffu, bv, off);
                int   j2 = __shfl_down_sync(0xffffffffu, bj, off);
                if (v2 < bv || (v2 == bv && j2 < bj)) { bv = v2; bj = j2; }
            }
            if (lane == 0) { rv[pp][wid] = bv; ri[pp][wid] = bj; }
            __syncthreads();                       // the ONLY barrier per iter

            mu = rv[pp][0]; jstar = ri[pp][0];
            #pragma unroll
            for (int k = 1; k < 8; k++) {
                float v2 = rv[pp][k]; int j2 = ri[pp][k];
                if (v2 < mu || (v2 == mu && j2 < jstar)) { mu = v2; jstar = j2; }
            }
            i1 = y[jstar];
            if (i1 < 0) break;

            if ((jstar >> 2) == tid) scm |= 1u << (jstar & 3);
            crow = CT + (long)i1 * Q_;
            h = __ldg(crow + jstar) - v[jstar] - mu;  // overlaps next scan load
            pp ^= 1;
        }
        __syncthreads();   // all reads of y done before augment mutates it

        if (owns) {
            const int j0 = tid << 2;
            if (scm & 1u) v[j0 + 0] += d.x - mu;
            if (scm & 2u) v[j0 + 1] += d.y - mu;
            if (scm & 4u) v[j0 + 2] += d.z - mu;
            if (scm & 8u) v[j0 + 3] += d.w - mu;
        }

        if (tid == 0) {
            int j = jstar;
            while (true) {
                int i = pred[j];
                y[j] = i;
                int jn = x[i];
                x[i] = j;
                if (i == f) break;
                j = jn;
            }
        }
        __syncthreads();
    }

    for (int j = tid; j < Q_; j += 256) {
        int r = y[j];
        if (r >= 0) col[r] = j;
    }
    __syncthreads();

    if (tid < T_) {
        int c = col[tid];
        int r = 0;
        #pragma unroll 4
        for (int t2 = 0; t2 < T_; t2++) r += (col[t2] < c);
        const long base = (long)B_ * Q_ * T_;
        out[base + (long)b * T_ + r] = (float)c;                    // pred_idx
        out[base + (long)B_ * T_ + (long)b * T_ + r] = (float)tid;  // tgt_idx
    }
}

extern "C" void kernel_launch(void* const* d_in, const int* in_sizes, int n_in,
                              void* d_out, int out_size)
{
    const float* pred_logits = (const float*)d_in[0];
    const float* pred_boxes  = (const float*)d_in[1];
    const int*   tgt_labels  = (const int*)d_in[2];
    const float* tgt_boxes   = (const float*)d_in[3];
    float* out = (float*)d_out;

    dim3 grid1(NCH, B_);
    cost_kernel<<<grid1, 256>>>(pred_logits, pred_boxes, tgt_labels, tgt_boxes);
    hungarian_kernel<<<B_ + COPYB, 256>>>(out);
}

// round 9
// speedup vs baseline: 1.0356x; 1.0356x over previous
#include <cuda_runtime.h>
#include <cuda_bf16.h>

#define B_  64
#define Q_  900
#define T_  100
#define C_  256
#define INF_ 1e9f
#define NCH 29      // ceil(Q_/32); last chunk has 4 rows
#define COPYB 1024  // transpose-copy blocks appended to hungarian launch

// Transposed cost scratch [B, T, Q] for contiguous row access in Hungarian.
__device__ float g_costT[B_ * T_ * Q_];
// Per (b, chunk, target-row) packed partial min of RAW cost: [key:32 | col:32]
__device__ unsigned long long g_rowpart[B_ * NCH * T_];

__device__ __forceinline__ unsigned int f32_orderable(float f) {
    unsigned int b = __float_as_uint(f);
    return (b & 0x80000000u) ? ~b : (b | 0x80000000u);
}

// ---------------------------------------------------------------------------
// Phase 1: cost matrix (costT layout only) + per-chunk raw row argmin.
// grid (29, B), 256 threads.
// ---------------------------------------------------------------------------
__global__ __launch_bounds__(256) void cost_kernel(
    const float* __restrict__ logits,   // [B,Q,C]
    const float* __restrict__ pboxes,   // [B,Q,4] cxcywh
    const int*   __restrict__ labels,   // [B,T]
    const float* __restrict__ tboxes)   // [B,T,4] cxcywh
{
    const int b  = blockIdx.y;
    const int q0 = blockIdx.x * 32;
    const int qcnt = min(32, Q_ - q0);
    const int tid = threadIdx.x;

    __shared__ float slog[32][257];
    __shared__ float stile[32][100];
    __shared__ float stb[100][4];
    __shared__ int   slab[100];
    __shared__ float spb[32][4];

    {
        const float* lg = logits + ((long)b * Q_ + q0) * C_;
        for (int i = tid * 4; i < qcnt * C_; i += 256 * 4) {
            float4 vv = *reinterpret_cast<const float4*>(lg + i);
            int r = i >> 8, c = i & 255;
            slog[r][c + 0] = vv.x; slog[r][c + 1] = vv.y;
            slog[r][c + 2] = vv.z; slog[r][c + 3] = vv.w;
        }
    }
    for (int i = tid; i < T_ * 4; i += 256)
        stb[i >> 2][i & 3] = tboxes[(long)b * T_ * 4 + i];
    for (int i = tid; i < T_; i += 256)
        slab[i] = labels[(long)b * T_ + i];
    for (int i = tid; i < qcnt * 4; i += 256)
        spb[i >> 2][i & 3] = pboxes[((long)b * Q_ + q0) * 4 + i];
    __syncthreads();

    for (int idx = tid; idx < qcnt * T_; idx += 256) {
        int qi = idx / T_;
        int t  = idx - qi * T_;
        float pcx = spb[qi][0], pcy = spb[qi][1], pw = spb[qi][2], ph = spb[qi][3];
        float tcx = stb[t][0],  tcy = stb[t][1],  tw = stb[t][2],  th = stb[t][3];

        float l1 = fabsf(pcx - tcx) + fabsf(pcy - tcy) + fabsf(pw - tw) + fabsf(ph - th);

        float ax0 = pcx - 0.5f * pw, ay0 = pcy - 0.5f * ph;
        float ax1 = pcx + 0.5f * pw, ay1 = pcy + 0.5f * ph;
        float bx0 = tcx - 0.5f * tw, by0 = tcy - 0.5f * th;
        float bx1 = tcx + 0.5f * tw, by1 = tcy + 0.5f * th;

        float areaA = (ax1 - ax0) * (ay1 - ay0);
        float areaB = (bx1 - bx0) * (by1 - by0);
        float ltx = fmaxf(ax0, bx0), lty = fmaxf(ay0, by0);
        float rbx = fminf(ax1, bx1), rby = fminf(ay1, by1);
        float iw = fmaxf(rbx - ltx, 0.f), ih = fmaxf(rby - lty, 0.f);
        float inter = iw * ih;
        float uni = areaA + areaB - inter;
        float iou = inter / uni;
        float ex0 = fminf(ax0, bx0), ey0 = fminf(ay0, by0);
        float ex1 = fmaxf(ax1, bx1), ey1 = fmaxf(ay1, by1);
        float enc = fmaxf(ex1 - ex0, 0.f) * fmaxf(ey1 - ey0, 0.f);
        float giou = iou - (enc - uni) / enc;

        stile[qi][t] = -slog[qi][slab[t]] + l1 - giou;
    }
    __syncthreads();

    // per-chunk target-row argmin of RAW cost -> packed partial (no atomics)
    if (tid < T_) {
        float best = INF_; int bq = 0;
        for (int qi = 0; qi < qcnt; qi++) {
            float c = stile[qi][tid];
            if (c < best) { best = c; bq = q0 + qi; }
        }
        g_rowpart[((long)b * NCH + blockIdx.x) * T_ + tid] =
            ((unsigned long long)f32_orderable(best) << 32) | (unsigned int)bq;
    }

    // transposed write, float4 over qi (900 % 4 == 0 -> aligned)
    for (int idx = tid; idx < T_ * 8; idx += 256) {
        int t   = idx >> 3;
        int seg = idx & 7;
        if (seg * 4 < qcnt) {
            float4 vv = make_float4(stile[seg * 4 + 0][t], stile[seg * 4 + 1][t],
                                    stile[seg * 4 + 2][t], stile[seg * 4 + 3][t]);
            *reinterpret_cast<float4*>(
                g_costT + ((long)b * T_ + t) * Q_ + q0 + seg * 4) = vv;
        }
    }
}

// ---------------------------------------------------------------------------
// Phase 2: blocks [0,64): JV Hungarian per batch (R4-proven path, v=0 init).
//          blocks [64,64+COPYB): costT -> [B,Q,T] d_out transpose copy
//          (1024 blocks -> BW-bound, hidden under hungarian's latency).
// ---------------------------------------------------------------------------
__global__ __launch_bounds__(256) void hungarian_kernel(float* __restrict__ out)
{
    const int tid = threadIdx.x;

    if (blockIdx.x >= B_) {
        // ----- transpose copy path (verified bit-exact in R8) -----
        __shared__ float tile[32][104];
        const int bc = blockIdx.x - B_;
        for (int tileId = bc; tileId < B_ * NCH; tileId += COPYB) {
            const int b  = tileId / NCH;
            const int ch = tileId - b * NCH;
            const int q0 = ch * 32;
            const int qcnt = min(32, Q_ - q0);
            for (int idx = tid; idx < T_ * 8; idx += 256) {
                int t = idx >> 3, seg = idx & 7;
                if (seg * 4 < qcnt) {
                    float4 vv = *reinterpret_cast<const float4*>(
                        g_costT + ((long)b * T_ + t) * Q_ + q0 + seg * 4);
                    tile[seg * 4 + 0][t] = vv.x; tile[seg * 4 + 1][t] = vv.y;
                    tile[seg * 4 + 2][t] = vv.z; tile[seg * 4 + 3][t] = vv.w;
                }
            }
            __syncthreads();
            for (int idx = tid; idx < qcnt * 25; idx += 256) {
                int qi = idx / 25, s = idx - qi * 25;
                float4 vv = make_float4(tile[qi][4 * s + 0], tile[qi][4 * s + 1],
                                        tile[qi][4 * s + 2], tile[qi][4 * s + 3]);
                *reinterpret_cast<float4*>(
                    out + ((long)(b * Q_ + q0 + qi)) * T_ + 4 * s) = vv;
            }
            __syncthreads();
        }
        return;
    }

    // ----- Hungarian path: byte-identical algorithm to R4 (passed 3x) -----
    const int b    = blockIdx.x;
    const int wid  = tid >> 5, lane = tid & 31;
    const float* CT = g_costT + (long)b * T_ * Q_;
    const bool owns = (tid < Q_ / 4);

    __shared__ float v[Q_];
    __shared__ int   pred[Q_];
    __shared__ int   y[Q_];
    __shared__ int   x[T_];
    __shared__ float rv[2][8];
    __shared__ int   ri[2][8];
    __shared__ int   col[T_];
    __shared__ int   rmin[T_];
    __shared__ int   freeRows[T_];
    __shared__ int   s_nfree;

    for (int j = tid; j < Q_; j += 256) { v[j] = 0.f; y[j] = -1; }

    if (tid < T_) {
        const unsigned long long* rp = g_rowpart + (long)b * NCH * T_ + tid;
        unsigned long long m = rp[0];
        #pragma unroll
        for (int c = 1; c < NCH; c++) {
            unsigned long long pk = rp[(long)c * T_];
            if (pk < m) m = pk;
        }
        rmin[tid] = (int)(unsigned int)(m & 0xFFFFFFFFULL);
    }
    __syncthreads();

    if (tid == 0) {
        int nf = 0;
        for (int i = 0; i < T_; i++) {
            int j = rmin[i];
            if (y[j] < 0) { y[j] = i; x[i] = j; }
            else          { x[i] = -1; freeRows[nf++] = i; }
        }
        s_nfree = nf;
    }
    __syncthreads();
    const int nfree = s_nfree;

    for (int fi = 0; fi < nfree; fi++) {
        const int f = freeRows[fi];
        float4 d = make_float4(INF_, INF_, INF_, INF_);
        unsigned int scm = 0;
        int   i1 = f;
        float h  = 0.f;
        const float* crow = CT + (long)f * Q_;
        float mu; int jstar;
        int pp = 0;

        while (true) {
            float bv = INF_; int bj = 0x7fffffff;
            if (owns) {
                const int j0 = tid << 2;
                float4 cv = __ldg((const float4*)(crow) + tid);
                float4 vv = *((const float4*)v + tid);
                if (!(scm & 1u)) {
                    float nd = cv.x - vv.x - h;
                    if (nd < d.x) { d.x = nd; pred[j0 + 0] = i1; }
                    if (d.x < bv) { bv = d.x; bj = j0 + 0; }
                }
                if (!(scm & 2u)) {
                    float nd = cv.y - vv.y - h;
                    if (nd < d.y) { d.y = nd; pred[j0 + 1] = i1; }
                    if (d.y < bv) { bv = d.y; bj = j0 + 1; }
                }
                if (!(scm & 4u)) {
                    float nd = cv.z - vv.z - h;
                    if (nd < d.z) { d.z = nd; pred[j0 + 2] = i1; }
                    if (d.z < bv) { bv = d.z; bj = j0 + 2; }
                }
                if (!(scm & 8u)) {
                    float nd = cv.w - vv.w - h;
                    if (nd < d.w) { d.w = nd; pred[j0 + 3] = i1; }
                    if (d.w < bv) { bv = d.w; bj = j0 + 3; }
                }
            }
            #pragma unroll
            for (int off = 16; off; off >>= 1) {
                float v2 = __shfl_down_sync(0xffffffffu, bv, off);
                int   j2 = __shfl_down_sync(0xffffffffu, bj, off);
                if (v2 < bv || (v2 == bv && j2 < bj)) { bv = v2; bj = j2; }
            }
            if (lane == 0) { rv[pp][wid] = bv; ri[pp][wid] = bj; }
            __syncthreads();                       // the ONLY barrier per iter

            mu = rv[pp][0]; jstar = ri[pp][0];
            #pragma unroll
            for (int k = 1; k < 8; k++) {
                float v2 = rv[pp][k]; int j2 = ri[pp][k];
                if (v2 < mu || (v2 == mu && j2 < jstar)) { mu = v2; jstar = j2; }
            }
            i1 = y[jstar];
            if (i1 < 0) break;

            if ((jstar >> 2) == tid) scm |= 1u << (jstar & 3);
            crow = CT + (long)i1 * Q_;
            h = __ldg(crow + jstar) - v[jstar] - mu;
            pp ^= 1;
        }
        __syncthreads();

        if (owns) {
            const int j0 = tid << 2;
            if (scm & 1u) v[j0 + 0] += d.x - mu;
            if (scm & 2u) v[j0 + 1] += d.y - mu;
            if (scm & 4u) v[j0 + 2] += d.z - mu;
            if (scm & 8u) v[j0 + 3] += d.w - mu;
        }

        if (tid == 0) {
            int j = jstar;
            while (true) {
                int i = pred[j];
                y[j] = i;
                int jn = x[i];
                x[i] = j;
                if (i == f) break;
                j = jn;
            }
        }
        __syncthreads();
    }

    for (int j = tid; j < Q_; j += 256) {
        int r = y[j];
        if (r >= 0) col[r] = j;
    }
    __syncthreads();

    if (tid < T_) {
        int c = col[tid];
        int r = 0;
        #pragma unroll 4
        for (int t2 = 0; t2 < T_; t2++) r += (col[t2] < c);
        const long base = (long)B_ * Q_ * T_;
        out[base + (long)b * T_ + r] = (float)c;                    // pred_idx
        out[base + (long)B_ * T_ + (long)b * T_ + r] = (float)tid;  // tgt_idx
    }
}

extern "C" void kernel_launch(void* const* d_in, const int* in_sizes, int n_in,
                              void* d_out, int out_size)
{
    const float* pred_logits = (const float*)d_in[0];
    const float* pred_boxes  = (const float*)d_in[1];
    const int*   tgt_labels  = (const int*)d_in[2];
    const float* tgt_boxes   = (const float*)d_in[3];
    float* out = (float*)d_out;

    dim3 grid1(NCH, B_);
    cost_kernel<<<grid1, 256>>>(pred_logits, pred_boxes, tgt_labels, tgt_boxes);
    hungarian_kernel<<<B_ + COPYB, 256>>>(out);
}

// round 11
// speedup vs baseline: 1.1364x; 1.0974x over previous
#include <cuda_runtime.h>
#include <cuda_bf16.h>

#define B_  64
#define Q_  900
#define T_  100
#define C_  256
#define INF_ 1e9f
#define QT  16    // q-rows per cost tile
#define NCH 57    // ceil(Q_/16); last chunk has 4 rows

// Transposed cost scratch [B, T, Q] for contiguous row access in Hungarian.
__device__ float g_costT[B_ * T_ * Q_];
// Per (b, chunk, target-row) packed partial min of RAW cost: [key:32 | col:32]
__device__ unsigned long long g_rowpart[B_ * NCH * T_];

__device__ __forceinline__ unsigned int f32_orderable(float f) {
    unsigned int b = __float_as_uint(f);
    return (b & 0x80000000u) ? ~b : (b | 0x80000000u);
}

// ---------------------------------------------------------------------------
// Phase 1: cost matrix (both layouts) + per-chunk raw row argmin.
// grid (57, B), 256 threads. 16-q tiles -> ~24KB smem -> ~9 blocks/SM.
// ---------------------------------------------------------------------------
__global__ __launch_bounds__(256) void cost_kernel(
    const float* __restrict__ logits,   // [B,Q,C]
    const float* __restrict__ pboxes,   // [B,Q,4] cxcywh
    const int*   __restrict__ labels,   // [B,T]
    const float* __restrict__ tboxes,   // [B,T,4] cxcywh
    float* __restrict__ cost)           // [B,Q,T] (d_out region 0)
{
    const int b  = blockIdx.y;
    const int q0 = blockIdx.x * QT;
    const int qcnt = min(QT, Q_ - q0);
    const int tid = threadIdx.x;

    __shared__ float slog[QT][257];      // padded
    __shared__ float stile[QT][100];
    __shared__ float stb[100][4];
    __shared__ int   slab[100];
    __shared__ float spb[QT][4];

    {
        const float* lg = logits + ((long)b * Q_ + q0) * C_;
        for (int i = tid * 4; i < qcnt * C_; i += 256 * 4) {
            float4 vv = *reinterpret_cast<const float4*>(lg + i);
            int r = i >> 8, c = i & 255;
            slog[r][c + 0] = vv.x; slog[r][c + 1] = vv.y;
            slog[r][c + 2] = vv.z; slog[r][c + 3] = vv.w;
        }
    }
    for (int i = tid; i < T_ * 4; i += 256)
        stb[i >> 2][i & 3] = tboxes[(long)b * T_ * 4 + i];
    for (int i = tid; i < T_; i += 256)
        slab[i] = labels[(long)b * T_ + i];
    for (int i = tid; i < qcnt * 4; i += 256)
        spb[i >> 2][i & 3] = pboxes[((long)b * Q_ + q0) * 4 + i];
    __syncthreads();

    for (int idx = tid; idx < qcnt * T_; idx += 256) {
        int qi = idx / T_;
        int t  = idx - qi * T_;
        float pcx = spb[qi][0], pcy = spb[qi][1], pw = spb[qi][2], ph = spb[qi][3];
        float tcx = stb[t][0],  tcy = stb[t][1],  tw = stb[t][2],  th = stb[t][3];

        float l1 = fabsf(pcx - tcx) + fabsf(pcy - tcy) + fabsf(pw - tw) + fabsf(ph - th);

        float ax0 = pcx - 0.5f * pw, ay0 = pcy - 0.5f * ph;
        float ax1 = pcx + 0.5f * pw, ay1 = pcy + 0.5f * ph;
        float bx0 = tcx - 0.5f * tw, by0 = tcy - 0.5f * th;
        float bx1 = tcx + 0.5f * tw, by1 = tcy + 0.5f * th;

        float areaA = (ax1 - ax0) * (ay1 - ay0);
        float areaB = (bx1 - bx0) * (by1 - by0);
        float ltx = fmaxf(ax0, bx0), lty = fmaxf(ay0, by0);
        float rbx = fminf(ax1, bx1), rby = fminf(ay1, by1);
        float iw = fmaxf(rbx - ltx, 0.f), ih = fmaxf(rby - lty, 0.f);
        float inter = iw * ih;
        float uni = areaA + areaB - inter;
        float iou = inter / uni;
        float ex0 = fminf(ax0, bx0), ey0 = fminf(ay0, by0);
        float ex1 = fmaxf(ax1, bx1), ey1 = fmaxf(ay1, by1);
        float enc = fmaxf(ex1 - ex0, 0.f) * fmaxf(ey1 - ey0, 0.f);
        float giou = iou - (enc - uni) / enc;

        float cval = -slog[qi][slab[t]] + l1 - giou;
        stile[qi][t] = cval;
        cost[((long)(b * Q_ + q0 + qi)) * T_ + t] = cval;   // coalesced over t
    }
    __syncthreads();

    // per-chunk target-row argmin of RAW cost -> packed partial (no atomics)
    if (tid < T_) {
        float best = INF_; int bq = 0;
        for (int qi = 0; qi < qcnt; qi++) {
            float c = stile[qi][tid];
            if (c < best) { best = c; bq = q0 + qi; }
        }
        g_rowpart[((long)b * NCH + blockIdx.x) * T_ + tid] =
            ((unsigned long long)f32_orderable(best) << 32) | (unsigned int)bq;
    }

    // transposed write, float4 over qi (900 % 4 == 0 -> aligned)
    for (int idx = tid; idx < T_ * 4; idx += 256) {
        int t   = idx >> 2;
        int seg = idx & 3;
        if (seg * 4 < qcnt) {
            float4 vv = make_float4(stile[seg * 4 + 0][t], stile[seg * 4 + 1][t],
                                    stile[seg * 4 + 2][t], stile[seg * 4 + 3][t]);
            *reinterpret_cast<float4*>(
                g_costT + ((long)b * T_ + t) * Q_ + q0 + seg * 4) = vv;
        }
    }
}

// ---------------------------------------------------------------------------
// Phase 2: JV Hungarian, one 256-thread block per batch (R4-proven path).
// ---------------------------------------------------------------------------
__global__ __launch_bounds__(256) void hungarian_kernel(float* __restrict__ out)
{
    const int b    = blockIdx.x;
    const int tid  = threadIdx.x;
    const int wid  = tid >> 5, lane = tid & 31;
    const float* CT = g_costT + (long)b * T_ * Q_;
    const bool owns = (tid < Q_ / 4);   // 225 scan threads, 4 contiguous cols each

    __shared__ float v[Q_];
    __shared__ int   pred[Q_];
    __shared__ int   y[Q_];      // col -> row (-1 free)
    __shared__ int   x[T_];      // row -> col
    __shared__ float rv[2][8];
    __shared__ int   ri[2][8];
    __shared__ int   col[T_];
    __shared__ int   rmin[T_];
    __shared__ int   freeRows[T_];
    __shared__ int   s_nfree;

    for (int j = tid; j < Q_; j += 256) { v[j] = 0.f; y[j] = -1; }

    if (tid < T_) {
        const unsigned long long* rp = g_rowpart + (long)b * NCH * T_ + tid;
        unsigned long long m = rp[0];
        for (int c = 1; c < NCH; c++) {
            unsigned long long pk = rp[(long)c * T_];
            if (pk < m) m = pk;
        }
        rmin[tid] = (int)(unsigned int)(m & 0xFFFFFFFFULL);
    }
    __syncthreads();

    if (tid == 0) {
        int nf = 0;
        for (int i = 0; i < T_; i++) {
            int j = rmin[i];
            if (y[j] < 0) { y[j] = i; x[i] = j; }
            else          { x[i] = -1; freeRows[nf++] = i; }
        }
        s_nfree = nf;
    }
    __syncthreads();
    const int nfree = s_nfree;

    for (int fi = 0; fi < nfree; fi++) {
        const int f = freeRows[fi];
        float4 d = make_float4(INF_, INF_, INF_, INF_);
        unsigned int scm = 0;
        int   i1 = f;
        float h  = 0.f;
        const float* crow = CT + (long)f * Q_;
        float mu; int jstar;
        int pp = 0;

        while (true) {
            float bv = INF_; int bj = 0x7fffffff;
            if (owns) {
                const int j0 = tid << 2;
                float4 cv = __ldg((const float4*)(crow) + tid);
                float4 vv = *((const float4*)v + tid);
                if (!(scm & 1u)) {
                    float nd = cv.x - vv.x - h;
                    if (nd < d.x) { d.x = nd; pred[j0 + 0] = i1; }
                    if (d.x < bv) { bv = d.x; bj = j0 + 0; }
                }
                if (!(scm & 2u)) {
                    float nd = cv.y - vv.y - h;
                    if (nd < d.y) { d.y = nd; pred[j0 + 1] = i1; }
                    if (d.y < bv) { bv = d.y; bj = j0 + 1; }
                }
                if (!(scm & 4u)) {
                    float nd = cv.z - vv.z - h;
                    if (nd < d.z) { d.z = nd; pred[j0 + 2] = i1; }
                    if (d.z < bv) { bv = d.z; bj = j0 + 2; }
                }
                if (!(scm & 8u)) {
                    float nd = cv.w - vv.w - h;
                    if (nd < d.w) { d.w = nd; pred[j0 + 3] = i1; }
                    if (d.w < bv) { bv = d.w; bj = j0 + 3; }
                }
            }
            #pragma unroll
            for (int off = 16; off; off >>= 1) {
                float v2 = __shfl_down_sync(0xffffffffu, bv, off);
                int   j2 = __shfl_down_sync(0xffffffffu, bj, off);
                if (v2 < bv || (v2 == bv && j2 < bj)) { bv = v2; bj = j2; }
            }
            if (lane == 0) { rv[pp][wid] = bv; ri[pp][wid] = bj; }
            __syncthreads();                       // the ONLY barrier per iter

            mu = rv[pp][0]; jstar = ri[pp][0];
            #pragma unroll
            for (int k = 1; k < 8; k++) {
                float v2 = rv[pp][k]; int j2 = ri[pp][k];
                if (v2 < mu || (v2 == mu && j2 < jstar)) { mu = v2; jstar = j2; }
            }
            i1 = y[jstar];
            if (i1 < 0) break;

            if ((jstar >> 2) == tid) scm |= 1u << (jstar & 3);
            crow = CT + (long)i1 * Q_;
            h = __ldg(crow + jstar) - v[jstar] - mu;
            pp ^= 1;
        }
        __syncthreads();

        if (owns) {
            const int j0 = tid << 2;
            if (scm & 1u) v[j0 + 0] += d.x - mu;
            if (scm & 2u) v[j0 + 1] += d.y - mu;
            if (scm & 4u) v[j0 + 2] += d.z - mu;
            if (scm & 8u) v[j0 + 3] += d.w - mu;
        }

        if (tid == 0) {
            int j = jstar;
            while (true) {
                int i = pred[j];
                y[j] = i;
                int jn = x[i];
                x[i] = j;
                if (i == f) break;
                j = jn;
            }
        }
        __syncthreads();
    }

    for (int j = tid; j < Q_; j += 256) {
        int r = y[j];
        if (r >= 0) col[r] = j;
    }
    __syncthreads();

    if (tid < T_) {
        int c = col[tid];
        int r = 0;
        #pragma unroll 4
        for (int t2 = 0; t2 < T_; t2++) r += (col[t2] < c);
        const long base = (long)B_ * Q_ * T_;
        out[base + (long)b * T_ + r] = (float)c;                    // pred_idx
        out[base + (long)B_ * T_ + (long)b * T_ + r] = (float)tid;  // tgt_idx
    }
}

extern "C" void kernel_launch(void* const* d_in, const int* in_sizes, int n_in,
                              void* d_out, int out_size)
{
    const float* pred_logits = (const float*)d_in[0];
    const float* pred_boxes  = (const float*)d_in[1];
    const int*   tgt_labels  = (const int*)d_in[2];
    const float* tgt_boxes   = (const float*)d_in[3];
    float* out = (float*)d_out;

    dim3 grid1(NCH, B_);
    cost_kernel<<<grid1, 256>>>(pred_logits, pred_boxes, tgt_labels, tgt_boxes, out);
    hungarian_kernel<<<B_, 256>>>(out);
}

// round 12
// speedup vs baseline: 1.1692x; 1.0288x over previous
#include <cuda_runtime.h>
#include <cuda_bf16.h>

#define B_  64
#define Q_  900
#define T_  100
#define C_  256
#define INF_ 1e9f
#define QT  16    // q-rows per cost tile
#define NCH 57    // ceil(Q_/16); last chunk has 4 rows

// Transposed cost scratch [B, T, Q] for contiguous row access in Hungarian.
__device__ float g_costT[B_ * T_ * Q_];
// Per (b, chunk, target-row) packed partial min of RAW cost: [key:32 | col:32]
__device__ unsigned long long g_rowpart[B_ * NCH * T_];

__device__ __forceinline__ unsigned int f32_orderable(float f) {
    unsigned int b = __float_as_uint(f);
    return (b & 0x80000000u) ? ~b : (b | 0x80000000u);
}

// ---------------------------------------------------------------------------
// Phase 1: cost matrix (both layouts) + per-chunk raw row argmin.
// grid (57, B), 256 threads. (unchanged from R11 passing kernel)
// ---------------------------------------------------------------------------
__global__ __launch_bounds__(256) void cost_kernel(
    const float* __restrict__ logits,   // [B,Q,C]
    const float* __restrict__ pboxes,   // [B,Q,4] cxcywh
    const int*   __restrict__ labels,   // [B,T]
    const float* __restrict__ tboxes,   // [B,T,4] cxcywh
    float* __restrict__ cost)           // [B,Q,T] (d_out region 0)
{
    const int b  = blockIdx.y;
    const int q0 = blockIdx.x * QT;
    const int qcnt = min(QT, Q_ - q0);
    const int tid = threadIdx.x;

    __shared__ float slog[QT][257];      // padded
    __shared__ float stile[QT][100];
    __shared__ float stb[100][4];
    __shared__ int   slab[100];
    __shared__ float spb[QT][4];

    {
        const float* lg = logits + ((long)b * Q_ + q0) * C_;
        for (int i = tid * 4; i < qcnt * C_; i += 256 * 4) {
            float4 vv = *reinterpret_cast<const float4*>(lg + i);
            int r = i >> 8, c = i & 255;
            slog[r][c + 0] = vv.x; slog[r][c + 1] = vv.y;
            slog[r][c + 2] = vv.z; slog[r][c + 3] = vv.w;
        }
    }
    for (int i = tid; i < T_ * 4; i += 256)
        stb[i >> 2][i & 3] = tboxes[(long)b * T_ * 4 + i];
    for (int i = tid; i < T_; i += 256)
        slab[i] = labels[(long)b * T_ + i];
    for (int i = tid; i < qcnt * 4; i += 256)
        spb[i >> 2][i & 3] = pboxes[((long)b * Q_ + q0) * 4 + i];
    __syncthreads();

    for (int idx = tid; idx < qcnt * T_; idx += 256) {
        int qi = idx / T_;
        int t  = idx - qi * T_;
        float pcx = spb[qi][0], pcy = spb[qi][1], pw = spb[qi][2], ph = spb[qi][3];
        float tcx = stb[t][0],  tcy = stb[t][1],  tw = stb[t][2],  th = stb[t][3];

        float l1 = fabsf(pcx - tcx) + fabsf(pcy - tcy) + fabsf(pw - tw) + fabsf(ph - th);

        float ax0 = pcx - 0.5f * pw, ay0 = pcy - 0.5f * ph;
        float ax1 = pcx + 0.5f * pw, ay1 = pcy + 0.5f * ph;
        float bx0 = tcx - 0.5f * tw, by0 = tcy - 0.5f * th;
        float bx1 = tcx + 0.5f * tw, by1 = tcy + 0.5f * th;

        float areaA = (ax1 - ax0) * (ay1 - ay0);
        float areaB = (bx1 - bx0) * (by1 - by0);
        float ltx = fmaxf(ax0, bx0), lty = fmaxf(ay0, by0);
        float rbx = fminf(ax1, bx1), rby = fminf(ay1, by1);
        float iw = fmaxf(rbx - ltx, 0.f), ih = fmaxf(rby - lty, 0.f);
        float inter = iw * ih;
        float uni = areaA + areaB - inter;
        float iou = inter / uni;
        float ex0 = fminf(ax0, bx0), ey0 = fminf(ay0, by0);
        float ex1 = fmaxf(ax1, bx1), ey1 = fmaxf(ay1, by1);
        float enc = fmaxf(ex1 - ex0, 0.f) * fmaxf(ey1 - ey0, 0.f);
        float giou = iou - (enc - uni) / enc;

        float cval = -slog[qi][slab[t]] + l1 - giou;
        stile[qi][t] = cval;
        cost[((long)(b * Q_ + q0 + qi)) * T_ + t] = cval;   // coalesced over t
    }
    __syncthreads();

    // per-chunk target-row argmin of RAW cost -> packed partial (no atomics)
    if (tid < T_) {
        float best = INF_; int bq = 0;
        for (int qi = 0; qi < qcnt; qi++) {
            float c = stile[qi][tid];
            if (c < best) { best = c; bq = q0 + qi; }
        }
        g_rowpart[((long)b * NCH + blockIdx.x) * T_ + tid] =
            ((unsigned long long)f32_orderable(best) << 32) | (unsigned int)bq;
    }

    // transposed write, float4 over qi (900 % 4 == 0 -> aligned)
    for (int idx = tid; idx < T_ * 4; idx += 256) {
        int t   = idx >> 2;
        int seg = idx & 3;
        if (seg * 4 < qcnt) {
            float4 vv = make_float4(stile[seg * 4 + 0][t], stile[seg * 4 + 1][t],
                                    stile[seg * 4 + 2][t], stile[seg * 4 + 3][t]);
            *reinterpret_cast<float4*>(
                g_costT + ((long)b * T_ + t) * Q_ + q0 + seg * 4) = vv;
        }
    }
}

// ---------------------------------------------------------------------------
// Phase 2: JV Hungarian, one 256-thread block per batch.
// R12 deltas: redux+ballot warp argmin; unrolled rmin reduction.
// ---------------------------------------------------------------------------
__global__ __launch_bounds__(256) void hungarian_kernel(float* __restrict__ out)
{
    const int b    = blockIdx.x;
    const int tid  = threadIdx.x;
    const int wid  = tid >> 5, lane = tid & 31;
    const float* CT = g_costT + (long)b * T_ * Q_;
    const bool owns = (tid < Q_ / 4);   // 225 scan threads, 4 contiguous cols each

    __shared__ float v[Q_];
    __shared__ int   pred[Q_];
    __shared__ int   y[Q_];      // col -> row (-1 free)
    __shared__ int   x[T_];      // row -> col
    __shared__ float rv[2][8];
    __shared__ int   ri[2][8];
    __shared__ int   col[T_];
    __shared__ int   rmin[T_];
    __shared__ int   freeRows[T_];
    __shared__ int   s_nfree;

    for (int j = tid; j < Q_; j += 256) { v[j] = 0.f; y[j] = -1; }

    if (tid < T_) {
        const unsigned long long* rp = g_rowpart + (long)b * NCH * T_ + tid;
        unsigned long long m = rp[0];
        #pragma unroll
        for (int c = 1; c < NCH; c++) {
            unsigned long long pk = rp[(long)c * T_];
            if (pk < m) m = pk;
        }
        rmin[tid] = (int)(unsigned int)(m & 0xFFFFFFFFULL);
    }
    __syncthreads();

    if (tid == 0) {
        int nf = 0;
        for (int i = 0; i < T_; i++) {
            int j = rmin[i];
            if (y[j] < 0) { y[j] = i; x[i] = j; }
            else          { x[i] = -1; freeRows[nf++] = i; }
        }
        s_nfree = nf;
    }
    __syncthreads();
    const int nfree = s_nfree;

    for (int fi = 0; fi < nfree; fi++) {
        const int f = freeRows[fi];
        float4 d = make_float4(INF_, INF_, INF_, INF_);
        unsigned int scm = 0;
        int   i1 = f;
        float h  = 0.f;
        const float* crow = CT + (long)f * Q_;
        float mu; int jstar;
        int pp = 0;

        while (true) {
            float bv = INF_; int bj = 0x7fffffff;
            if (owns) {
                const int j0 = tid << 2;
                float4 cv = __ldg((const float4*)(crow) + tid);
                float4 vv = *((const float4*)v + tid);
                if (!(scm & 1u)) {
                    float nd = cv.x - vv.x - h;
                    if (nd < d.x) { d.x = nd; pred[j0 + 0] = i1; }
                    if (d.x < bv) { bv = d.x; bj = j0 + 0; }
                }
                if (!(scm & 2u)) {
                    float nd = cv.y - vv.y - h;
                    if (nd < d.y) { d.y = nd; pred[j0 + 1] = i1; }
                    if (d.y < bv) { bv = d.y; bj = j0 + 1; }
                }
                if (!(scm & 4u)) {
                    float nd = cv.z - vv.z - h;
                    if (nd < d.z) { d.z = nd; pred[j0 + 2] = i1; }
                    if (d.z < bv) { bv = d.z; bj = j0 + 2; }
                }
                if (!(scm & 8u)) {
                    float nd = cv.w - vv.w - h;
                    if (nd < d.w) { d.w = nd; pred[j0 + 3] = i1; }
                    if (d.w < bv) { bv = d.w; bj = j0 + 3; }
                }
            }
            // warp argmin: redux over orderable key, ballot picks lowest lane
            // (= lowest column; exact tie-break equivalence with shuffle tree)
            {
                unsigned int key = f32_orderable(bv);
                unsigned int mk  = __reduce_min_sync(0xffffffffu, key);
                unsigned int bal = __ballot_sync(0xffffffffu, key == mk);
                int src = __ffs(bal) - 1;
                bv = __shfl_sync(0xffffffffu, bv, src);
                bj = __shfl_sync(0xffffffffu, bj, src);
            }
            if (lane == 0) { rv[pp][wid] = bv; ri[pp][wid] = bj; }
            __syncthreads();                       // the ONLY barrier per iter

            mu = rv[pp][0]; jstar = ri[pp][0];
            #pragma unroll
            for (int k = 1; k < 8; k++) {
                float v2 = rv[pp][k]; int j2 = ri[pp][k];
                if (v2 < mu || (v2 == mu && j2 < jstar)) { mu = v2; jstar = j2; }
            }
            i1 = y[jstar];
            if (i1 < 0) break;

            if ((jstar >> 2) == tid) scm |= 1u << (jstar & 3);
            crow = CT + (long)i1 * Q_;
            h = __ldg(crow + jstar) - v[jstar] - mu;
            pp ^= 1;
        }
        __syncthreads();

        if (owns) {
            const int j0 = tid << 2;
            if (scm & 1u) v[j0 + 0] += d.x - mu;
            if (scm & 2u) v[j0 + 1] += d.y - mu;
            if (scm & 4u) v[j0 + 2] += d.z - mu;
            if (scm & 8u) v[j0 + 3] += d.w - mu;
        }

        if (tid == 0) {
            int j = jstar;
            while (true) {
                int i = pred[j];
                y[j] = i;
                int jn = x[i];
                x[i] = j;
                if (i == f) break;
                j = jn;
            }
        }
        __syncthreads();
    }

    for (int j = tid; j < Q_; j += 256) {
        int r = y[j];
        if (r >= 0) col[r] = j;
    }
    __syncthreads();

    if (tid < T_) {
        int c = col[tid];
        int r = 0;
        #pragma unroll 4
        for (int t2 = 0; t2 < T_; t2++) r += (col[t2] < c);
        const long base = (long)B_ * Q_ * T_;
        out[base + (long)b * T_ + r] = (float)c;                    // pred_idx
        out[base + (long)B_ * T_ + (long)b * T_ + r] = (float)tid;  // tgt_idx
    }
}

extern "C" void kernel_launch(void* const* d_in, const int* in_sizes, int n_in,
                              void* d_out, int out_size)
{
    const float* pred_logits = (const float*)d_in[0];
    const float* pred_boxes  = (const float*)d_in[1];
    const int*   tgt_labels  = (const int*)d_in[2];
    const float* tgt_boxes   = (const float*)d_in[3];
    float* out = (float*)d_out;

    dim3 grid1(NCH, B_);
    cost_kernel<<<grid1, 256>>>(pred_logits, pred_boxes, tgt_labels, tgt_boxes, out);
    hungarian_kernel<<<B_, 256>>>(out);
}